// round 6
// baseline (speedup 1.0000x reference)
#include <cuda_runtime.h>
#include <cuda_fp16.h>
#include <math.h>
#include <stdint.h>

#define D_MODEL 1024
#define N_EXP   8
#define N_TOK   4096
#define FFN_H   2048
#define CAP     N_TOK

// ---------------- device scratch ----------------
__device__ int   g_cnt[N_EXP];
__device__ int   g_tok[N_EXP * CAP];
__device__ int   g_slot[N_EXP * CAP];
__device__ float g_wt[N_EXP * CAP];
__device__ float g_probs[N_TOK * N_EXP];

__device__ __align__(16) __half g_x_f16[(size_t)N_TOK * D_MODEL];
__device__ __align__(16) __half g_w1_f16[(size_t)N_EXP * FFN_H * D_MODEL];
__device__ __align__(16) __half g_w2_f16[(size_t)N_EXP * D_MODEL * FFN_H];
__device__ __align__(16) __half g_h_f16[(size_t)2 * N_TOK * FFN_H];

// ---------------- portable PTX helpers ----------------
__device__ __forceinline__ uint32_t smem_u32(const void* p) {
    uint32_t a;
    asm("{ .reg .u64 t; cvta.to.shared.u64 t, %1; cvt.u32.u64 %0, t; }" : "=r"(a) : "l"(p));
    return a;
}

#define CP16(dst, src) \
    asm volatile("cp.async.cg.shared.global [%0], [%1], 16;" :: "r"(dst), "l"(src))
#define CP_COMMIT() asm volatile("cp.async.commit_group;" ::: "memory")
#define CP_WAIT0()  asm volatile("cp.async.wait_group 0;" ::: "memory")

#define LDSM4(r, addr) \
    asm volatile("ldmatrix.sync.aligned.m8n8.x4.shared.b16 {%0,%1,%2,%3}, [%4];" \
                 : "=r"((r)[0]), "=r"((r)[1]), "=r"((r)[2]), "=r"((r)[3]) : "r"(addr))

#define MMA16816(c, a, b0, b1) \
    asm volatile("mma.sync.aligned.m16n8k16.row.col.f32.f16.f16.f32 " \
                 "{%0,%1,%2,%3}, {%4,%5,%6,%7}, {%8,%9}, {%0,%1,%2,%3};" \
                 : "+f"((c)[0]), "+f"((c)[1]), "+f"((c)[2]), "+f"((c)[3]) \
                 : "r"((a)[0]), "r"((a)[1]), "r"((a)[2]), "r"((a)[3]), \
                   "r"(b0), "r"(b1))

__device__ __forceinline__ uint32_t swz(uint32_t off) { return off ^ ((off >> 3) & 0x70); }

// ---------------- geometry ----------------
#define BKT 64
// GEMM1: BM=64, BN=128 — stage = A 8KB + B 16KB
#define G1_OFF_B 8192
#define G1_STAGE 24576
#define G1_SMEM (2 * G1_STAGE)
// GEMM2: BM=64, BN=64 — stage = A 8KB + B 8KB
#define G2_OFF_B 8192
#define G2_STAGE 16384
#define G2_SMEM (2 * G2_STAGE)

// ---------------- init ----------------
__global__ void zero_kernel(float4* out4, int n4) {
    int i = blockIdx.x * blockDim.x + threadIdx.x;
    if (i < n4) out4[i] = make_float4(0.f, 0.f, 0.f, 0.f);
    if (i < N_EXP) g_cnt[i] = 0;
}

// ---------------- router (warp/token) + fused x fp16 convert ----------------
__global__ __launch_bounds__(256) void router_kernel(const float4* __restrict__ x4,
                                                     const float4* __restrict__ rw4) {
    const int lane = threadIdx.x & 31;
    const int wid = threadIdx.x >> 5;
    const int n = blockIdx.x * 8 + wid;
    if (n >= N_TOK) return;

    const float4* xr = x4 + (size_t)n * (D_MODEL / 4);
    uint2* xo = (uint2*)(g_x_f16 + (size_t)n * D_MODEL);
    float part[N_EXP];
#pragma unroll
    for (int e = 0; e < N_EXP; e++) part[e] = 0.f;
#pragma unroll
    for (int i = 0; i < 8; i++) {
        float4 v = xr[lane + 32 * i];
        // fused fp32->fp16 convert of x
        __half2 p0 = __floats2half2_rn(v.x, v.y);
        __half2 p1 = __floats2half2_rn(v.z, v.w);
        uint2 pk;
        pk.x = *(uint32_t*)&p0; pk.y = *(uint32_t*)&p1;
        xo[lane + 32 * i] = pk;
#pragma unroll
        for (int e = 0; e < N_EXP; e++) {
            float4 w = rw4[e * (D_MODEL / 4) + lane + 32 * i];
            part[e] += v.x * w.x + v.y * w.y + v.z * w.z + v.w * w.w;
        }
    }
#pragma unroll
    for (int o = 16; o > 0; o >>= 1) {
#pragma unroll
        for (int e = 0; e < N_EXP; e++)
            part[e] += __shfl_xor_sync(0xFFFFFFFF, part[e], o);
    }
    if (lane == 0) {
        float m = part[0];
#pragma unroll
        for (int e = 1; e < N_EXP; e++) m = fmaxf(m, part[e]);
        float p[N_EXP], s = 0.f;
#pragma unroll
        for (int e = 0; e < N_EXP; e++) { p[e] = expf(part[e] - m); s += p[e]; }
        float inv = 1.f / s;
#pragma unroll
        for (int e = 0; e < N_EXP; e++) { p[e] *= inv; g_probs[n * N_EXP + e] = p[e]; }
        int i1 = 0;
#pragma unroll
        for (int e = 1; e < N_EXP; e++) if (part[e] > part[i1]) i1 = e;
        int i2 = (i1 == 0) ? 1 : 0;
#pragma unroll
        for (int e = 0; e < N_EXP; e++) if (e != i1 && part[e] > part[i2]) i2 = e;
        float denom = p[i1] + p[i2];
        int pos1 = atomicAdd(&g_cnt[i1], 1);
        g_tok[i1 * CAP + pos1] = n; g_slot[i1 * CAP + pos1] = 2 * n; g_wt[i1 * CAP + pos1] = p[i1] / denom;
        int pos2 = atomicAdd(&g_cnt[i2], 1);
        g_tok[i2 * CAP + pos2] = n; g_slot[i2 * CAP + pos2] = 2 * n + 1; g_wt[i2 * CAP + pos2] = p[i2] / denom;
    }
}

// ---------------- fused psum + aux loss ----------------
__global__ __launch_bounds__(256) void psumaux_kernel(float* out, int out_size) {
    const int lane = threadIdx.x & 31;
    const int e = threadIdx.x >> 5;   // 8 warps, one per expert
    float s = 0.f;
    for (int n = lane; n < N_TOK; n += 32) s += g_probs[n * N_EXP + e];
#pragma unroll
    for (int o = 16; o > 0; o >>= 1) s += __shfl_xor_sync(0xFFFFFFFF, s, o);
    __shared__ float ps[N_EXP];
    if (lane == 0) ps[e] = s;
    __syncthreads();
    if (threadIdx.x == 0) {
        float a = 0.f;
#pragma unroll
        for (int k = 0; k < N_EXP; k++) {
            float f = (float)g_cnt[k] / (float)(N_TOK * 2);
            float P = ps[k] / (float)N_TOK;
            a += f * P;
        }
        a *= (float)N_EXP;
        if (out_size > N_TOK * D_MODEL) out[N_TOK * D_MODEL] = a;
    }
}

// ---------------- fused fp32 -> fp16 convert for both weights ----------------
__global__ __launch_bounds__(256) void cvt_w_kernel(const float4* __restrict__ w1,
                                                    const float4* __restrict__ w2, int nw4) {
    int i = blockIdx.x * blockDim.x + threadIdx.x;
    float4 v;
    __half2* o2;
    if (i < nw4) {
        v = w1[i];
        o2 = (__half2*)g_w1_f16 + 2 * (size_t)i;
    } else if (i < 2 * nw4) {
        int j = i - nw4;
        v = w2[j];
        o2 = (__half2*)g_w2_f16 + 2 * (size_t)j;
    } else return;
    o2[0] = __floats2half2_rn(v.x, v.y);
    o2[1] = __floats2half2_rn(v.z, v.w);
}

// ============ grouped GEMM1: BM=64, BN=128, warp tile 32x32 ============
__device__ __forceinline__ void g1_load(uint32_t st, int lrA, int lcA, int lrB, int lcB,
                                        const __half* aP, const __half* bP, int k0) {
#pragma unroll
    for (int j = 0; j < 2; j++) {
        uint32_t off = (uint32_t)lrA * 128 + (lcA + j) * 16;
        CP16(st + swz(off), (const void*)(aP + k0 + (lcA + j) * 8));
    }
#pragma unroll
    for (int j = 0; j < 4; j++) {
        uint32_t off = (uint32_t)lrB * 128 + (lcB + j) * 16;
        CP16(st + G1_OFF_B + swz(off), (const void*)(bP + k0 + (lcB + j) * 8));
    }
    CP_COMMIT();
}

__device__ __forceinline__ void g1_compute(uint32_t sb, float acc[2][4][4],
                                           int wm, int wn, int lane) {
    const int arow = lane & 15, ahalf = lane >> 4;
    const int nrow = ((lane >> 4) & 1) * 8 + (lane & 7);
    const int bhalf = (lane >> 3) & 1;
#pragma unroll
    for (int kk = 0; kk < 4; kk++) {
        uint32_t ah[2][4], bf[2][4];
#pragma unroll
        for (int mi = 0; mi < 2; mi++) {
            uint32_t off = (uint32_t)(wm * 32 + mi * 16 + arow) * 128 + kk * 32 + ahalf * 16;
            LDSM4(ah[mi], sb + swz(off));
        }
#pragma unroll
        for (int p = 0; p < 2; p++) {
            uint32_t off = (uint32_t)(wn * 32 + p * 16 + nrow) * 128 + kk * 32 + bhalf * 16;
            LDSM4(bf[p], sb + G1_OFF_B + swz(off));
        }
#pragma unroll
        for (int mi = 0; mi < 2; mi++)
#pragma unroll
            for (int p = 0; p < 2; p++) {
                MMA16816(acc[mi][2 * p],     ah[mi], bf[p][0], bf[p][1]);
                MMA16816(acc[mi][2 * p + 1], ah[mi], bf[p][2], bf[p][3]);
            }
    }
}

__global__ __launch_bounds__(256, 3) void gemm1_mma(const float* __restrict__ b1) {
    const int e = blockIdx.z;
    const int cnt = g_cnt[e];
    const int row0 = blockIdx.y * 64;
    if (row0 >= cnt) return;
    const int col0 = blockIdx.x * 128;

    extern __shared__ char sm[];
    __shared__ int toks[64];
    __shared__ int slots[64];

    const int tid = threadIdx.x;
    if (tid < 64) {
        int r = row0 + tid;
        toks[tid]  = (r < cnt) ? g_tok[e * CAP + r]  : 0;
        slots[tid] = (r < cnt) ? g_slot[e * CAP + r] : -1;
    }
    __syncthreads();

    const uint32_t smb = smem_u32(sm);
    const int lrA = tid >> 2, lcA = (tid & 3) * 2;
    const int lrB = tid >> 1, lcB = (tid & 1) * 4;

    const __half* aP = g_x_f16 + (size_t)toks[lrA] * D_MODEL;
    const __half* bP = g_w1_f16 + ((size_t)e * FFN_H + col0 + lrB) * D_MODEL;

    float acc[2][4][4];
#pragma unroll
    for (int mi = 0; mi < 2; mi++)
#pragma unroll
        for (int ni = 0; ni < 4; ni++)
#pragma unroll
            for (int q = 0; q < 4; q++) acc[mi][ni][q] = 0.f;

    const int lane = tid & 31;
    const int wid = tid >> 5;
    const int wm = wid >> 2, wn = wid & 3;
    const int NT = D_MODEL / BKT;   // 16

    g1_load(smb, lrA, lcA, lrB, lcB, aP, bP, 0);

#pragma unroll 1
    for (int it = 0; it < NT; it++) {
        CP_WAIT0();
        __syncthreads();
        if (it + 1 < NT)
            g1_load(smb + ((it + 1) & 1) * G1_STAGE, lrA, lcA, lrB, lcB, aP, bP, (it + 1) * BKT);
        g1_compute(smb + (it & 1) * G1_STAGE, acc, wm, wn, lane);
        __syncthreads();
    }

    // epilogue: bias + silu + fp16 store
    const int gr = lane >> 2, gc2 = (lane & 3) * 2;
    const float* b1e = b1 + (size_t)e * FFN_H;
#pragma unroll
    for (int mi = 0; mi < 2; mi++) {
#pragma unroll
        for (int ni = 0; ni < 4; ni++) {
            int col = col0 + wn * 32 + ni * 8 + gc2;
            float bv0 = b1e[col], bv1 = b1e[col + 1];
#pragma unroll
            for (int half = 0; half < 2; half++) {
                int r = wm * 32 + mi * 16 + gr + half * 8;
                int slot = slots[r];
                if (slot >= 0) {
                    float v0 = acc[mi][ni][half * 2 + 0] + bv0;
                    float v1 = acc[mi][ni][half * 2 + 1] + bv1;
                    float s0 = v0 / (1.f + expf(-v0));
                    float s1 = v1 / (1.f + expf(-v1));
                    *(__half2*)(g_h_f16 + (size_t)slot * FFN_H + col) = __floats2half2_rn(s0, s1);
                }
            }
        }
    }
}

// ============ grouped GEMM2: BM=64, BN=64, warp tile 32x16 ============
__device__ __forceinline__ void g2_load(uint32_t st, int lr, int lc,
                                        const __half* aP, const __half* bP, int k0) {
#pragma unroll
    for (int j = 0; j < 2; j++) {
        uint32_t off = (uint32_t)lr * 128 + (lc + j) * 16;
        uint32_t so = swz(off);
        CP16(st + so, (const void*)(aP + k0 + (lc + j) * 8));
        CP16(st + G2_OFF_B + so, (const void*)(bP + k0 + (lc + j) * 8));
    }
    CP_COMMIT();
}

__device__ __forceinline__ void g2_compute(uint32_t sb, float acc[2][2][4],
                                           int wm, int wn, int lane) {
    const int arow = lane & 15, ahalf = lane >> 4;
    const int nrow = ((lane >> 4) & 1) * 8 + (lane & 7);
    const int bhalf = (lane >> 3) & 1;
#pragma unroll
    for (int kk = 0; kk < 4; kk++) {
        uint32_t ah[2][4], bf[4];
#pragma unroll
        for (int mi = 0; mi < 2; mi++) {
            uint32_t off = (uint32_t)(wm * 32 + mi * 16 + arow) * 128 + kk * 32 + ahalf * 16;
            LDSM4(ah[mi], sb + swz(off));
        }
        {
            uint32_t off = (uint32_t)(wn * 16 + nrow) * 128 + kk * 32 + bhalf * 16;
            LDSM4(bf, sb + G2_OFF_B + swz(off));
        }
#pragma unroll
        for (int mi = 0; mi < 2; mi++) {
            MMA16816(acc[mi][0], ah[mi], bf[0], bf[1]);
            MMA16816(acc[mi][1], ah[mi], bf[2], bf[3]);
        }
    }
}

__global__ __launch_bounds__(256, 4) void gemm2_mma(const float* __restrict__ b2,
                                                    float* __restrict__ out) {
    const int e = blockIdx.z;
    const int cnt = g_cnt[e];
    const int row0 = blockIdx.y * 64;
    if (row0 >= cnt) return;
    const int col0 = blockIdx.x * 64;

    extern __shared__ char sm[];
    __shared__ int   toks[64];
    __shared__ float wts[64];
    __shared__ int   slots[64];

    const int tid = threadIdx.x;
    if (tid < 64) {
        int r = row0 + tid;
        toks[tid]  = (r < cnt) ? g_tok[e * CAP + r]  : -1;
        slots[tid] = (r < cnt) ? g_slot[e * CAP + r] : 0;
        wts[tid]   = (r < cnt) ? g_wt[e * CAP + r]   : 0.f;
    }
    __syncthreads();

    const uint32_t smb = smem_u32(sm);
    const int lr = tid >> 2, lc = (tid & 3) * 2;

    const __half* aP = g_h_f16 + (size_t)slots[lr] * FFN_H;
    const __half* bP = g_w2_f16 + ((size_t)e * D_MODEL + col0 + lr) * FFN_H;

    float acc[2][2][4];
#pragma unroll
    for (int mi = 0; mi < 2; mi++)
#pragma unroll
        for (int ni = 0; ni < 2; ni++)
#pragma unroll
            for (int q = 0; q < 4; q++) acc[mi][ni][q] = 0.f;

    const int lane = tid & 31;
    const int wid = tid >> 5;
    const int wm = wid >> 2, wn = wid & 3;
    const int NT = FFN_H / BKT;   // 32

    g2_load(smb, lr, lc, aP, bP, 0);

#pragma unroll 1
    for (int it = 0; it < NT; it++) {
        CP_WAIT0();
        __syncthreads();
        if (it + 1 < NT)
            g2_load(smb + ((it + 1) & 1) * G2_STAGE, lr, lc, aP, bP, (it + 1) * BKT);
        g2_compute(smb + (it & 1) * G2_STAGE, acc, wm, wn, lane);
        __syncthreads();
    }

    // epilogue: weighted atomic scatter
    const int gr = lane >> 2, gc2 = (lane & 3) * 2;
    const float* b2e = b2 + (size_t)e * D_MODEL;
#pragma unroll
    for (int mi = 0; mi < 2; mi++) {
#pragma unroll
        for (int ni = 0; ni < 2; ni++) {
            int col = col0 + wn * 16 + ni * 8 + gc2;
            float bv0 = b2e[col], bv1 = b2e[col + 1];
#pragma unroll
            for (int half = 0; half < 2; half++) {
                int r = wm * 32 + mi * 16 + gr + half * 8;
                int tok = toks[r];
                if (tok >= 0) {
                    float wt = wts[r];
                    float v0 = (acc[mi][ni][half * 2 + 0] + bv0) * wt;
                    float v1 = (acc[mi][ni][half * 2 + 1] + bv1) * wt;
                    atomicAdd(out + (size_t)tok * D_MODEL + col,     v0);
                    atomicAdd(out + (size_t)tok * D_MODEL + col + 1, v1);
                }
            }
        }
    }
}

// ---------------- launch ----------------
extern "C" void kernel_launch(void* const* d_in, const int* in_sizes, int n_in,
                              void* d_out, int out_size) {
    const float* x  = (const float*)d_in[0];
    const float* rw = (const float*)d_in[1];
    const float* w1 = (const float*)d_in[2];
    const float* b1 = (const float*)d_in[3];
    const float* w2 = (const float*)d_in[4];
    const float* b2 = (const float*)d_in[5];
    float* out = (float*)d_out;

    cudaFuncSetAttribute(gemm1_mma, cudaFuncAttributeMaxDynamicSharedMemorySize, G1_SMEM);
    cudaFuncSetAttribute(gemm2_mma, cudaFuncAttributeMaxDynamicSharedMemorySize, G2_SMEM);

    const int n4 = N_TOK * D_MODEL / 4;
    zero_kernel<<<(n4 + 255) / 256, 256>>>((float4*)out, n4);

    const int nw4 = N_EXP * FFN_H * D_MODEL / 4;
    cvt_w_kernel<<<(2 * nw4 + 255) / 256, 256>>>((const float4*)w1, (const float4*)w2, nw4);

    router_kernel<<<N_TOK / 8, 256>>>((const float4*)x, (const float4*)rw);
    psumaux_kernel<<<1, 256>>>(out, out_size);

    dim3 g1(FFN_H / 128, N_TOK / 64, N_EXP);
    gemm1_mma<<<g1, 256, G1_SMEM>>>(b1);
    dim3 g2(D_MODEL / 64, N_TOK / 64, N_EXP);
    gemm2_mma<<<g2, 256, G2_SMEM>>>(b2, out);
}

// round 7
// speedup vs baseline: 1.0623x; 1.0623x over previous
#include <cuda_runtime.h>
#include <cuda_fp16.h>
#include <math.h>
#include <stdint.h>

#define D_MODEL 1024
#define N_EXP   8
#define N_TOK   4096
#define FFN_H   2048
#define CAP     N_TOK

// ---------------- device scratch ----------------
__device__ int   g_cnt[N_EXP];
__device__ int   g_tok[N_EXP * CAP];
__device__ int   g_slot[N_EXP * CAP];
__device__ float g_wt[N_EXP * CAP];
__device__ float g_probs[N_TOK * N_EXP];
__device__ float g_psum[N_EXP];

__device__ __align__(16) __half g_x_f16[(size_t)N_TOK * D_MODEL];
__device__ __align__(16) __half g_w1_f16[(size_t)N_EXP * FFN_H * D_MODEL];
__device__ __align__(16) __half g_w2_f16[(size_t)N_EXP * D_MODEL * FFN_H];
__device__ __align__(16) __half g_h_f16[(size_t)2 * N_TOK * FFN_H];
__device__ __align__(16) float  g_y[(size_t)2 * N_TOK * D_MODEL];   // per-slot GEMM2 out

// ---------------- portable PTX helpers ----------------
__device__ __forceinline__ uint32_t smem_u32(const void* p) {
    uint32_t a;
    asm("{ .reg .u64 t; cvta.to.shared.u64 t, %1; cvt.u32.u64 %0, t; }" : "=r"(a) : "l"(p));
    return a;
}

#define CP16(dst, src) \
    asm volatile("cp.async.cg.shared.global [%0], [%1], 16;" :: "r"(dst), "l"(src))
#define CP_COMMIT() asm volatile("cp.async.commit_group;" ::: "memory")
#define CP_WAIT0()  asm volatile("cp.async.wait_group 0;" ::: "memory")

#define LDSM4(r, addr) \
    asm volatile("ldmatrix.sync.aligned.m8n8.x4.shared.b16 {%0,%1,%2,%3}, [%4];" \
                 : "=r"((r)[0]), "=r"((r)[1]), "=r"((r)[2]), "=r"((r)[3]) : "r"(addr))

#define MMA16816(c, a, b0, b1) \
    asm volatile("mma.sync.aligned.m16n8k16.row.col.f32.f16.f16.f32 " \
                 "{%0,%1,%2,%3}, {%4,%5,%6,%7}, {%8,%9}, {%0,%1,%2,%3};" \
                 : "+f"((c)[0]), "+f"((c)[1]), "+f"((c)[2]), "+f"((c)[3]) \
                 : "r"((a)[0]), "r"((a)[1]), "r"((a)[2]), "r"((a)[3]), \
                   "r"(b0), "r"(b1))

__device__ __forceinline__ uint32_t swz(uint32_t off) { return off ^ ((off >> 3) & 0x70); }

// ---------------- tile geometry (R5-proven) ----------------
#define BM 128
#define BN 128
#define BKT 64
#define OFF_A 0
#define OFF_B 16384
#define STAGE_TOTAL 32768
#define SMEM_DYN (2 * STAGE_TOTAL)

// ---------------- fused w1/w2 fp16 convert + flag init ----------------
__global__ __launch_bounds__(256) void cvt_w_kernel(const float4* __restrict__ w1,
                                                    const float4* __restrict__ w2, int nw4) {
    int i = blockIdx.x * blockDim.x + threadIdx.x;
    if (blockIdx.x == 0 && threadIdx.x < N_EXP) {
        g_cnt[threadIdx.x] = 0;
        g_psum[threadIdx.x] = 0.f;
    }
    float4 v;
    __half2* o2;
    if (i < nw4) {
        v = w1[i];
        o2 = (__half2*)g_w1_f16 + 2 * (size_t)i;
    } else if (i < 2 * nw4) {
        int j = i - nw4;
        v = w2[j];
        o2 = (__half2*)g_w2_f16 + 2 * (size_t)j;
    } else return;
    o2[0] = __floats2half2_rn(v.x, v.y);
    o2[1] = __floats2half2_rn(v.z, v.w);
}

// ---------------- router (warp/token) + fused x cvt + block psum ----------------
__global__ __launch_bounds__(256) void router_kernel(const float4* __restrict__ x4,
                                                     const float4* __restrict__ rw4) {
    const int lane = threadIdx.x & 31;
    const int wid = threadIdx.x >> 5;
    const int n = blockIdx.x * 8 + wid;

    __shared__ float sp[8][N_EXP];

    const float4* xr = x4 + (size_t)n * (D_MODEL / 4);
    uint2* xo = (uint2*)(g_x_f16 + (size_t)n * D_MODEL);
    float part[N_EXP];
#pragma unroll
    for (int e = 0; e < N_EXP; e++) part[e] = 0.f;
#pragma unroll
    for (int i = 0; i < 8; i++) {
        float4 v = xr[lane + 32 * i];
        __half2 p0 = __floats2half2_rn(v.x, v.y);
        __half2 p1 = __floats2half2_rn(v.z, v.w);
        uint2 pk;
        pk.x = *(uint32_t*)&p0; pk.y = *(uint32_t*)&p1;
        xo[lane + 32 * i] = pk;
#pragma unroll
        for (int e = 0; e < N_EXP; e++) {
            float4 w = rw4[e * (D_MODEL / 4) + lane + 32 * i];
            part[e] += v.x * w.x + v.y * w.y + v.z * w.z + v.w * w.w;
        }
    }
#pragma unroll
    for (int o = 16; o > 0; o >>= 1) {
#pragma unroll
        for (int e = 0; e < N_EXP; e++)
            part[e] += __shfl_xor_sync(0xFFFFFFFF, part[e], o);
    }
    if (lane == 0) {
        float m = part[0];
#pragma unroll
        for (int e = 1; e < N_EXP; e++) m = fmaxf(m, part[e]);
        float p[N_EXP], s = 0.f;
#pragma unroll
        for (int e = 0; e < N_EXP; e++) { p[e] = expf(part[e] - m); s += p[e]; }
        float inv = 1.f / s;
#pragma unroll
        for (int e = 0; e < N_EXP; e++) { p[e] *= inv; sp[wid][e] = p[e]; }
        int i1 = 0;
#pragma unroll
        for (int e = 1; e < N_EXP; e++) if (part[e] > part[i1]) i1 = e;
        int i2 = (i1 == 0) ? 1 : 0;
#pragma unroll
        for (int e = 0; e < N_EXP; e++) if (e != i1 && part[e] > part[i2]) i2 = e;
        float denom = p[i1] + p[i2];
        int pos1 = atomicAdd(&g_cnt[i1], 1);
        g_tok[i1 * CAP + pos1] = n; g_slot[i1 * CAP + pos1] = 2 * n; g_wt[i1 * CAP + pos1] = p[i1] / denom;
        int pos2 = atomicAdd(&g_cnt[i2], 1);
        g_tok[i2 * CAP + pos2] = n; g_slot[i2 * CAP + pos2] = 2 * n + 1; g_wt[i2 * CAP + pos2] = p[i2] / denom;
    }
    __syncthreads();
    if (threadIdx.x < N_EXP) {
        float s = 0.f;
#pragma unroll
        for (int w = 0; w < 8; w++) s += sp[w][threadIdx.x];
        atomicAdd(&g_psum[threadIdx.x], s);
    }
}

// ---------------- stage loader / compute (R5-proven) ----------------
__device__ __forceinline__ void load_stage(uint32_t st, int lr, int lc0,
                                           const __half* a, const __half* b, int k0) {
#pragma unroll
    for (int j = 0; j < 4; j++) {
        uint32_t off = (uint32_t)lr * 128 + (lc0 + j) * 16;
        uint32_t so = swz(off);
        CP16(st + OFF_A + so, (const void*)(a + k0 + (lc0 + j) * 8));
        CP16(st + OFF_B + so, (const void*)(b + k0 + (lc0 + j) * 8));
    }
    CP_COMMIT();
}

__device__ __forceinline__ void compute_stage(uint32_t sb, float acc[4][4][4],
                                              int wm, int wn, int lane) {
    const int arow = lane & 15, ahalf = lane >> 4;
    const int nrow = ((lane >> 4) & 1) * 8 + (lane & 7);
    const int bhalf = (lane >> 3) & 1;
#pragma unroll
    for (int kk = 0; kk < 4; kk++) {
        uint32_t ah[4][4], bf[2][4];
#pragma unroll
        for (int mi = 0; mi < 4; mi++) {
            uint32_t off = (uint32_t)(wm * 64 + mi * 16 + arow) * 128 + kk * 32 + ahalf * 16;
            LDSM4(ah[mi], sb + OFF_A + swz(off));
        }
#pragma unroll
        for (int p = 0; p < 2; p++) {
            uint32_t off = (uint32_t)(wn * 32 + p * 16 + nrow) * 128 + kk * 32 + bhalf * 16;
            LDSM4(bf[p], sb + OFF_B + swz(off));
        }
#pragma unroll
        for (int mi = 0; mi < 4; mi++) {
#pragma unroll
            for (int p = 0; p < 2; p++) {
                MMA16816(acc[mi][2 * p],     ah[mi], bf[p][0], bf[p][1]);
                MMA16816(acc[mi][2 * p + 1], ah[mi], bf[p][2], bf[p][3]);
            }
        }
    }
}

// ============ grouped GEMM1: h[slot] = silu(x[tok] @ w1[e]^T + b1[e]) ============
__global__ __launch_bounds__(256, 2) void gemm1_mma(const float* __restrict__ b1) {
    const int e = blockIdx.z;
    const int cnt = g_cnt[e];
    const int row0 = blockIdx.y * BM;
    if (row0 >= cnt) return;
    const int col0 = blockIdx.x * BN;

    extern __shared__ char sm[];
    __shared__ int toks[BM];
    __shared__ int slots[BM];

    const int tid = threadIdx.x;
    if (tid < BM) {
        int r = row0 + tid;
        toks[tid]  = (r < cnt) ? g_tok[e * CAP + r]  : 0;
        slots[tid] = (r < cnt) ? g_slot[e * CAP + r] : -1;
    }
    __syncthreads();

    const uint32_t smb = smem_u32(sm);
    const int lr = tid >> 1;
    const int lc0 = (tid & 1) * 4;

    const __half* aP = g_x_f16 + (size_t)toks[lr] * D_MODEL;
    const __half* bP = g_w1_f16 + ((size_t)e * FFN_H + col0 + lr) * D_MODEL;

    float acc[4][4][4];
#pragma unroll
    for (int mi = 0; mi < 4; mi++)
#pragma unroll
        for (int ni = 0; ni < 4; ni++)
#pragma unroll
            for (int q = 0; q < 4; q++) acc[mi][ni][q] = 0.f;

    const int lane = tid & 31;
    const int wid = tid >> 5;
    const int wm = wid >> 2, wn = wid & 3;
    const int NT = D_MODEL / BKT;   // 16

    load_stage(smb, lr, lc0, aP, bP, 0);

#pragma unroll 1
    for (int it = 0; it < NT; it++) {
        CP_WAIT0();
        __syncthreads();
        if (it + 1 < NT)
            load_stage(smb + ((it + 1) & 1) * STAGE_TOTAL, lr, lc0, aP, bP, (it + 1) * BKT);
        compute_stage(smb + (it & 1) * STAGE_TOTAL, acc, wm, wn, lane);
        __syncthreads();
    }

    // epilogue: bias + silu + fp16 store
    const int gr = lane >> 2, gc2 = (lane & 3) * 2;
    const float* b1e = b1 + (size_t)e * FFN_H;
#pragma unroll
    for (int mi = 0; mi < 4; mi++) {
#pragma unroll
        for (int ni = 0; ni < 4; ni++) {
            int col = col0 + wn * 32 + ni * 8 + gc2;
            float bv0 = b1e[col], bv1 = b1e[col + 1];
#pragma unroll
            for (int half = 0; half < 2; half++) {
                int r = wm * 64 + mi * 16 + gr + half * 8;
                int slot = slots[r];
                if (slot >= 0) {
                    float v0 = acc[mi][ni][half * 2 + 0] + bv0;
                    float v1 = acc[mi][ni][half * 2 + 1] + bv1;
                    float s0 = v0 / (1.f + expf(-v0));
                    float s1 = v1 / (1.f + expf(-v1));
                    *(__half2*)(g_h_f16 + (size_t)slot * FFN_H + col) = __floats2half2_rn(s0, s1);
                }
            }
        }
    }
}

// ============ grouped GEMM2: y[slot] = wt * (h[slot] @ w2[e]^T + b2[e]) ============
__global__ __launch_bounds__(256, 2) void gemm2_mma(const float* __restrict__ b2) {
    const int e = blockIdx.z;
    const int cnt = g_cnt[e];
    const int row0 = blockIdx.y * BM;
    if (row0 >= cnt) return;
    const int col0 = blockIdx.x * BN;

    extern __shared__ char sm[];
    __shared__ float wts[BM];
    __shared__ int   slots[BM];

    const int tid = threadIdx.x;
    if (tid < BM) {
        int r = row0 + tid;
        slots[tid] = (r < cnt) ? g_slot[e * CAP + r] : -1;
        wts[tid]   = (r < cnt) ? g_wt[e * CAP + r]   : 0.f;
    }
    __syncthreads();

    const uint32_t smb = smem_u32(sm);
    const int lr = tid >> 1;
    const int lc0 = (tid & 1) * 4;

    const int aslot = (slots[lr] < 0) ? 0 : slots[lr];
    const __half* aP = g_h_f16 + (size_t)aslot * FFN_H;
    const __half* bP = g_w2_f16 + ((size_t)e * D_MODEL + col0 + lr) * FFN_H;

    float acc[4][4][4];
#pragma unroll
    for (int mi = 0; mi < 4; mi++)
#pragma unroll
        for (int ni = 0; ni < 4; ni++)
#pragma unroll
            for (int q = 0; q < 4; q++) acc[mi][ni][q] = 0.f;

    const int lane = tid & 31;
    const int wid = tid >> 5;
    const int wm = wid >> 2, wn = wid & 3;
    const int NT = FFN_H / BKT;   // 32

    load_stage(smb, lr, lc0, aP, bP, 0);

#pragma unroll 1
    for (int it = 0; it < NT; it++) {
        CP_WAIT0();
        __syncthreads();
        if (it + 1 < NT)
            load_stage(smb + ((it + 1) & 1) * STAGE_TOTAL, lr, lc0, aP, bP, (it + 1) * BKT);
        compute_stage(smb + (it & 1) * STAGE_TOTAL, acc, wm, wn, lane);
        __syncthreads();
    }

    // epilogue: weighted + biased store to per-slot scratch (no atomics)
    const int gr = lane >> 2, gc2 = (lane & 3) * 2;
    const float* b2e = b2 + (size_t)e * D_MODEL;
#pragma unroll
    for (int mi = 0; mi < 4; mi++) {
#pragma unroll
        for (int ni = 0; ni < 4; ni++) {
            int col = col0 + wn * 32 + ni * 8 + gc2;
            float bv0 = b2e[col], bv1 = b2e[col + 1];
#pragma unroll
            for (int half = 0; half < 2; half++) {
                int r = wm * 64 + mi * 16 + gr + half * 8;
                int slot = slots[r];
                if (slot >= 0) {
                    float wt = wts[r];
                    float2 v;
                    v.x = (acc[mi][ni][half * 2 + 0] + bv0) * wt;
                    v.y = (acc[mi][ni][half * 2 + 1] + bv1) * wt;
                    *(float2*)(g_y + (size_t)slot * D_MODEL + col) = v;
                }
            }
        }
    }
}

// ---------------- combine: out[n] = y[2n] + y[2n+1]; + aux loss ----------------
__global__ __launch_bounds__(256) void combine_kernel(float4* __restrict__ out4,
                                                      float* __restrict__ out,
                                                      int out_size) {
    int i = blockIdx.x * blockDim.x + threadIdx.x;
    const int D4 = D_MODEL / 4;
    if (i < N_TOK * D4) {
        int n = i / D4, rem = i - n * D4;
        const float4* ya = (const float4*)g_y + (size_t)(2 * n) * D4 + rem;
        const float4* yb = (const float4*)g_y + (size_t)(2 * n + 1) * D4 + rem;
        float4 a = *ya, b = *yb;
        float4 r;
        r.x = a.x + b.x; r.y = a.y + b.y; r.z = a.z + b.z; r.w = a.w + b.w;
        out4[i] = r;
    }
    if (blockIdx.x == 0 && threadIdx.x == 0 && out_size > N_TOK * D_MODEL) {
        float a = 0.f;
#pragma unroll
        for (int e = 0; e < N_EXP; e++) {
            float f = (float)g_cnt[e] / (float)(N_TOK * 2);
            float P = g_psum[e] / (float)N_TOK;
            a += f * P;
        }
        out[N_TOK * D_MODEL] = a * (float)N_EXP;
    }
}

// ---------------- launch ----------------
extern "C" void kernel_launch(void* const* d_in, const int* in_sizes, int n_in,
                              void* d_out, int out_size) {
    const float* x  = (const float*)d_in[0];
    const float* rw = (const float*)d_in[1];
    const float* w1 = (const float*)d_in[2];
    const float* b1 = (const float*)d_in[3];
    const float* w2 = (const float*)d_in[4];
    const float* b2 = (const float*)d_in[5];
    float* out = (float*)d_out;

    cudaFuncSetAttribute(gemm1_mma, cudaFuncAttributeMaxDynamicSharedMemorySize, SMEM_DYN);
    cudaFuncSetAttribute(gemm2_mma, cudaFuncAttributeMaxDynamicSharedMemorySize, SMEM_DYN);

    const int nw4 = N_EXP * FFN_H * D_MODEL / 4;
    cvt_w_kernel<<<(2 * nw4 + 255) / 256, 256>>>((const float4*)w1, (const float4*)w2, nw4);

    router_kernel<<<N_TOK / 8, 256>>>((const float4*)x, (const float4*)rw);

    dim3 g1(FFN_H / BN, N_TOK / BM, N_EXP);
    gemm1_mma<<<g1, 256, SMEM_DYN>>>(b1);
    dim3 g2(D_MODEL / BN, N_TOK / BM, N_EXP);
    gemm2_mma<<<g2, 256, SMEM_DYN>>>(b2);

    const int nc = N_TOK * (D_MODEL / 4);
    combine_kernel<<<(nc + 255) / 256, 256>>>((float4*)out, out, out_size);
}